// round 15
// baseline (speedup 1.0000x reference)
#include <cuda_runtime.h>

#define HW   4096
#define NC   128
#define CR   32
#define KK   49

#define GEN_BLOCKS    512
#define INV_BLOCKS    512
#define GEN_PER_BATCH 128

// scratch for generated per-pixel kernels: [B=4][49][64*64]
__device__ float g_kernel[4 * KK * HW];
// producer/consumer flags (self-resetting each run -> graph-replay safe)
__device__ int g_done[4];
__device__ int g_inv_done;

// ---------------------------------------------------------------------------
// Fused kernel. Blocks 0..511: GEN (batch b = bid>>7, 32 px each, 4 warp-parts).
// Blocks 512..1023: INV (R14 body: 8-row x 64-col x 8-ch tile, 4 px/thread).
// INV waits per-batch on g_done[b] AFTER its x-halo load (halo is independent
// of g_kernel, so the spin is overlapped with useful work + gen execution).
// ---------------------------------------------------------------------------
__global__ __launch_bounds__(128, 4) void fused_kernel(
    const float* __restrict__ x,  const float* __restrict__ w1,
    const float* __restrict__ b1, const float* __restrict__ gamma,
    const float* __restrict__ beta, const float* __restrict__ mean,
    const float* __restrict__ var,  const float* __restrict__ w2,
    const float* __restrict__ b2,   float* __restrict__ out)
{
    __shared__ __align__(16) float smem[9856];   // 38.5 KB pool (union of roles)
    __shared__ float s_scale[CR], s_shift[CR];

    const int bx  = blockIdx.x;
    const int tid = threadIdx.x;

    if (bx < GEN_BLOCKS) {
        // ================= GEN role =================
        float* w1t  = smem;          // [128c][32o]   4096 floats
        float* w2tt = smem + 4096;   // [52t][32o]    1664 floats (padded)
        float* fbuf = smem + 5760;   // [4][32o][32p] 4096 floats

        // ---- staging, vectorized ----
        {
            const float4* w1f4 = (const float4*)w1;
            #pragma unroll
            for (int j = 0; j < 8; j++) {
                int idx = tid + j * 128;        // 0..1023
                float4 w = w1f4[idx];
                int o  = idx >> 5;              // 0..31
                int cq = idx & 31;              // c-quad
                w1t[(cq * 4 + 0) * CR + o] = w.x;
                w1t[(cq * 4 + 1) * CR + o] = w.y;
                w1t[(cq * 4 + 2) * CR + o] = w.z;
                w1t[(cq * 4 + 3) * CR + o] = w.w;
            }
            const float4* w2f4 = (const float4*)w2;
            float4* w2t4 = (float4*)w2tt;
            #pragma unroll
            for (int j = 0; j < 4; j++) {
                int idx = tid + j * 128;        // 0..511, need 416
                if (idx < 392)       w2t4[idx] = w2f4[idx];
                else if (idx < 416)  w2t4[idx] = make_float4(0.f, 0.f, 0.f, 0.f);
            }
            if (tid < CR) {
                float sc = gamma[tid] * rsqrtf(var[tid] + 1e-5f);
                s_scale[tid] = sc;
                s_shift[tid] = fmaf(b1[tid], sc, beta[tid] - mean[tid] * sc);
            }
        }
        __syncthreads();

        const int pix_l = tid & 31;
        const int part  = tid >> 5;            // warp id 0..3
        const int pixel = bx * 32 + pix_l;
        const int b     = pixel >> 12;         // == bx>>7: batch-ordered bids
        const int hw    = pixel & (HW - 1);

        // ---- stage 1: partial 1x1 conv over this part's 32 channels ----
        float fp[CR];
        #pragma unroll
        for (int o = 0; o < CR; o++) fp[o] = 0.f;

        const float* xp = x + ((size_t)(b * NC + part * 32)) * HW + hw;
        #pragma unroll 8
        for (int c = 0; c < 32; c++) {
            float xv = xp[(size_t)c * HW];
            const float4* wr = (const float4*)&w1t[(part * 32 + c) * CR];
            #pragma unroll
            for (int o4 = 0; o4 < 8; o4++) {
                float4 w = wr[o4];
                fp[o4*4+0] = fmaf(w.x, xv, fp[o4*4+0]);
                fp[o4*4+1] = fmaf(w.y, xv, fp[o4*4+1]);
                fp[o4*4+2] = fmaf(w.z, xv, fp[o4*4+2]);
                fp[o4*4+3] = fmaf(w.w, xv, fp[o4*4+3]);
            }
        }
        {
            float* fb = fbuf + part * (CR * 32) + pix_l;
            #pragma unroll
            for (int o = 0; o < CR; o++) fb[o * 32] = fp[o];
        }
        __syncthreads();

        // ---- stage 2: combine partials + BN + ReLU ----
        float f[CR];
        #pragma unroll
        for (int o = 0; o < CR; o++) {
            float v = fbuf[0*(CR*32) + o*32 + pix_l]
                    + fbuf[1*(CR*32) + o*32 + pix_l]
                    + fbuf[2*(CR*32) + o*32 + pix_l]
                    + fbuf[3*(CR*32) + o*32 + pix_l];
            v = fmaf(v, s_scale[o], s_shift[o]);
            f[o] = fmaxf(v, 0.f);
        }

        // ---- stage 3: this part's 13 kernel outputs ----
        const int t0 = part * 13;
        float* kp = g_kernel + (size_t)b * KK * HW + hw;
        #pragma unroll
        for (int tt = 0; tt < 13; tt++) {
            int t = t0 + tt;
            const float4* wr = (const float4*)&w2tt[t * CR];
            float a0 = 0.f, a1 = 0.f, a2 = 0.f, a3 = 0.f;
            #pragma unroll
            for (int o4 = 0; o4 < 8; o4++) {
                float4 w = wr[o4];
                a0 = fmaf(w.x, f[o4*4+0], a0);
                a1 = fmaf(w.y, f[o4*4+1], a1);
                a2 = fmaf(w.z, f[o4*4+2], a2);
                a3 = fmaf(w.w, f[o4*4+3], a3);
            }
            if (t < KK)
                kp[(size_t)t * HW] = (a0 + a1) + (a2 + a3) + b2[t];
        }

        // ---- publish: release g_kernel[b] ----
        __threadfence();
        __syncthreads();
        if (tid == 0) atomicAdd(&g_done[b], 1);

    } else {
        // ================= INV role =================
        float* xs = smem;                      // [8ch][14r][72c] 8064 floats

        const int bid2 = bx - GEN_BLOCKS;      // 0..511
        const int b  = bid2 >> 7;
        const int ht = (bid2 >> 4) & 7;        // 8 row-tiles of 8
        const int cg = bid2 & 15;              // 16 groups of 8 channels
        const int h0 = ht * 8;
        const int c0 = cg * 8;

        const int row  = tid >> 4;             // 0..7 output row
        const int wloc = (tid & 15) * 4;       // 0,4,...,60

        // ---- halo main fill: 14 aligned float4 loads per thread ----
        #pragma unroll
        for (int it = 0; it < 14; it++) {
            int idx = tid + it * 128;          // 0..1791
            int ch  = idx / 224;
            int rem = idx - ch * 224;
            int r   = rem >> 4;
            int k   = rem & 15;
            int gr  = h0 - 3 + r;
            float4 v = make_float4(0.f, 0.f, 0.f, 0.f);
            if ((unsigned)gr < 64u)
                v = *(const float4*)(x + ((size_t)(b * NC + c0 + ch) << 12)
                                       + (gr << 6) + (k << 2));
            float* d = xs + ch * 1008 + r * 72 + 3 + (k << 2);
            d[0] = v.x; d[1] = v.y; d[2] = v.z; d[3] = v.w;
        }
        // ---- halo edges: cols 0..2 and 67..71 -> zero ----
        #pragma unroll
        for (int it = 0; it < 7; it++) {
            int idx = tid + it * 128;          // 0..895
            int ch  = idx / 112;
            int rem = idx - ch * 112;
            int r   = rem >> 3;
            int e   = rem & 7;
            int col = (e < 3) ? e : (64 + e);
            xs[ch * 1008 + r * 72 + col] = 0.f;
        }

        // ---- wait for gen of this batch (acquire) ----
        if (tid == 0) {
            while (*(volatile int*)&g_done[b] < GEN_PER_BATCH) __nanosleep(100);
            __threadfence();
        }
        __syncthreads();   // also covers halo stores

        const float* kpix = g_kernel + (size_t)b * KK * HW + (h0 + row) * 64 + wloc;

        float acc[8][4];
        #pragma unroll
        for (int cc = 0; cc < 8; cc++)
            #pragma unroll
            for (int p = 0; p < 4; p++) acc[cc][p] = 0.f;

        // prefetch kernel tap-row 0
        float4 kr[7], krn[7];
        #pragma unroll
        for (int j = 0; j < 7; j++)
            kr[j] = *(const float4*)(kpix + (size_t)j * HW);

        #pragma unroll 1
        for (int i = 0; i < 7; i++) {
            if (i < 6) {
                #pragma unroll
                for (int j = 0; j < 7; j++)
                    krn[j] = *(const float4*)(kpix + (size_t)((i + 1) * 7 + j) * HW);
            }
            const float* xrow = xs + (row + i) * 72 + wloc;
            #pragma unroll
            for (int cc = 0; cc < 8; cc++) {
                const float* rp = xrow + cc * 1008;
                float4 u0 = *(const float4*)(rp);
                float4 u1 = *(const float4*)(rp + 4);
                float2 u2 = *(const float2*)(rp + 8);
                float va[10] = {u0.x,u0.y,u0.z,u0.w, u1.x,u1.y,u1.z,u1.w, u2.x,u2.y};
                float a0 = acc[cc][0], a1 = acc[cc][1], a2 = acc[cc][2], a3 = acc[cc][3];
                #pragma unroll
                for (int j = 0; j < 7; j++) {
                    a0 = fmaf(kr[j].x, va[j],     a0);
                    a1 = fmaf(kr[j].y, va[j + 1], a1);
                    a2 = fmaf(kr[j].z, va[j + 2], a2);
                    a3 = fmaf(kr[j].w, va[j + 3], a3);
                }
                acc[cc][0] = a0; acc[cc][1] = a1; acc[cc][2] = a2; acc[cc][3] = a3;
            }
            #pragma unroll
            for (int j = 0; j < 7; j++) kr[j] = krn[j];
        }

        const size_t out_pix = (size_t)(h0 + row) * 64 + wloc;
        #pragma unroll
        for (int cc = 0; cc < 8; cc++) {
            float4 res;
            res.x = acc[cc][0]; res.y = acc[cc][1];
            res.z = acc[cc][2]; res.w = acc[cc][3];
            *(float4*)(out + ((size_t)(b * NC + c0 + cc) << 12) + out_pix) = res;
        }

        // ---- last inv block resets flags for the next graph replay ----
        __threadfence();
        __syncthreads();
        if (tid == 0) {
            int n = atomicAdd(&g_inv_done, 1);
            if (n == INV_BLOCKS - 1) {
                atomicExch(&g_done[0], 0);
                atomicExch(&g_done[1], 0);
                atomicExch(&g_done[2], 0);
                atomicExch(&g_done[3], 0);
                atomicExch(&g_inv_done, 0);
            }
        }
    }
}

extern "C" void kernel_launch(void* const* d_in, const int* in_sizes, int n_in,
                              void* d_out, int out_size)
{
    const float* x     = (const float*)d_in[0];
    const float* w1    = (const float*)d_in[1];
    const float* b1    = (const float*)d_in[2];
    const float* gamma = (const float*)d_in[3];
    const float* beta  = (const float*)d_in[4];
    const float* mean  = (const float*)d_in[5];
    const float* var   = (const float*)d_in[6];
    const float* w2    = (const float*)d_in[7];
    const float* b2    = (const float*)d_in[8];

    fused_kernel<<<GEN_BLOCKS + INV_BLOCKS, 128>>>(
        x, w1, b1, gamma, beta, mean, var, w2, b2, (float*)d_out);
}